// round 15
// baseline (speedup 1.0000x reference)
#include <cuda_runtime.h>
#include <math.h>

#define HH 1024
#define WW 1024
#define NPIX (HH * WW)
#define NWORDS 32                 // packed words per row
#define RPB 8                     // output rows per block in kernel A
#define LROWS (RPB + 4)           // seg rows loaded: r0-2 .. r0+9
#define EROWS (RPB + 2)           // edge rows computed: r0-1 .. r0+8

#define B_BLOCKS 128              // x-blocks per image in kernel B
#define B_THREADS 1024
#define B_ITERS (NPIX / 4 / (B_BLOCKS * B_THREADS))   // 2
#define NBLK_TOTAL (B_BLOCKS * 2)                     // 256
#define FIXSCALE 1048576.0        // 2^20 fixed point

// Scratch (no allocations allowed anywhere)
__device__ unsigned int       g_edgebits[2][HH * NWORDS];  // 256 KB
__device__ unsigned char      g_D[2][NPIX];                // 2 MB: D2 code 0..4, 255=unresolved
__device__ unsigned long long g_acc;   // [63:48] block count, [47:0] fixed-point sum

__device__ __forceinline__ unsigned horiz3(unsigned wv, unsigned wl, unsigned wr) {
    return wv & ((wv << 1) | (wl >> 31)) & ((wv >> 1) | (wr << 31));
}

// exact per-row nearest-edge distance from the packed edge bitmap (global),
// replicating the reference's 1e6 fp32 defaults bit-for-bit. Rare path only.
__device__ float row_g(const unsigned* __restrict__ row, int c)
{
    const int t = c >> 5, k = c & 31;
    const unsigned wc = row[t];
    const unsigned wl = (t > 0) ? row[t - 1] : 0u;
    const unsigned wr2 = (t < NWORDS - 1) ? row[t + 1] : 0u;
    const unsigned long long L = ((unsigned long long)wc << 32) | wl;   // pixel at bit 32+k
    const unsigned long long R = ((unsigned long long)wr2 << 32) | wc;  // pixel at bit k
    const unsigned long long lm = L & (~0ULL >> (31 - k));
    const unsigned long long rm = R & (~0ULL << k);
    float dl, dr;
    if (lm) {
        dl = (float)(__clzll((long long)lm) - (31 - k));
    } else {
        int tt = t - 2;
        while (tt >= 0 && row[tt] == 0u) tt--;
        if (tt >= 0) dl = (float)(c - (tt * 32 + (31 - __clz(row[tt]))));
        else         dl = (float)c + 1e6f;          // reference default, exact fp32
    }
    if (rm) {
        dr = (float)(__ffsll((long long)rm) - 1 - k);
    } else {
        int tt = t + 2;
        while (tt < NWORDS && row[tt] == 0u) tt++;
        if (tt < NWORDS) dr = (float)((tt * 32 + (__ffs(row[tt]) - 1)) - c);
        else             dr = 1e6f - (float)c;      // reference default, exact fp32
    }
    return fminf(fminf(dl, dr), 1e6f);
}

// WARP-COOPERATIVE exact column lower-envelope for one pixel (r,c).
// Round covering d = d0..d0+31: lane l takes d = d0 + l (lane 0 of round one
// is the d=0 base term). All row_g loads issue in parallel (MLP~32), one
// butterfly fmin-reduce per round; the exact prune (d0+32)^2 >= best ends it
// (identical candidate set to the reference; min is order-independent).
__device__ __noinline__ float warp_edt2(const unsigned* __restrict__ eb, int r, int c)
{
    const int lane = threadIdx.x & 31;
    float best = 3e37f;
    int d0 = 0;
    while (true) {
        const int d = d0 + lane;
        float cand = 3e37f;
        if (d == 0) {
            const float g = row_g(eb + r * NWORDS, c);
            cand = g * g;
        } else {
            float up = 3e37f, dn = 3e37f;
            if (r - d >= 0) { const float g = row_g(eb + (r - d) * NWORDS, c); up = g * g; }
            if (r + d < HH) { const float g = row_g(eb + (r + d) * NWORDS, c); dn = g * g; }
            cand = fminf(up, dn) + (float)(d * d);   // d*d exact in fp32 (d <= ~1055)
        }
        #pragma unroll
        for (int o = 16; o > 0; o >>= 1)
            cand = fminf(cand, __shfl_xor_sync(0xffffffffu, cand, o));
        best = fminf(best, cand);

        d0 += 32;
        const float nd = (float)d0;
        if (nd * nd >= best) break;                  // provably cannot improve
        if (r - d0 < 0 && r + d0 >= HH) break;       // all source rows covered
    }
    return best;
}

// ---------------------------------------------------------------------------
// Kernel A: bit-packed edges + per-row 1D distance + vertical depth-1 min,
// emitting a u8 code per pixel: D2 = min(g2[r], min(g2[r-1],g2[r+1])+1).
// D2 <= 4 proves global optimality (all d>=2 candidates >= 4) and D2 is then
// an exact small integer -> code 0..4; otherwise 255 (resolved exactly in B).
// ---------------------------------------------------------------------------
__global__ void __launch_bounds__(WW, 2) edges_rowdist_kernel(
    const float* __restrict__ preds, const float* __restrict__ targets)
{
    const int r0 = blockIdx.x * RPB;
    const int m  = blockIdx.y;
    const int j  = threadIdx.x;
    const float* __restrict__ seg = (m == 0) ? preds : targets;

    // reset the packed accumulator for this replay (stream-ordered before B)
    if (blockIdx.x == 0 && m == 0 && j == 0) g_acc = 0ULL;

    __shared__ unsigned shB[LROWS][NWORDS];
    __shared__ unsigned shE[EROWS][NWORDS];

    const int t = j >> 5, k = j & 31;

    // load LROWS rows (batched for MLP), ballot-pack to bits
    float v[LROWS];
    #pragma unroll
    for (int rr = 0; rr < LROWS; rr++) {
        const int row = r0 + rr - 2;
        v[rr] = (row >= 0 && row < HH) ? seg[row * WW + j] : 0.0f;
    }
    #pragma unroll
    for (int rr = 0; rr < LROWS; rr++) {
        const unsigned b = __ballot_sync(0xffffffffu, v[rr] == 1.0f);
        if (k == 0) shB[rr][t] = b;
    }
    __syncthreads();

    // EROWS*NWORDS = 320 threads compute one edge word each
    if (j < EROWS * NWORDS) {
        const int w  = j & (NWORDS - 1);
        const int rr = j >> 5;            // 0..9 -> edge row r0-1+rr
        const unsigned hp = horiz3(shB[rr][w],
                                   w > 0 ? shB[rr][w - 1] : 0u,
                                   w < NWORDS - 1 ? shB[rr][w + 1] : 0u);
        const unsigned hc = horiz3(shB[rr + 1][w],
                                   w > 0 ? shB[rr + 1][w - 1] : 0u,
                                   w < NWORDS - 1 ? shB[rr + 1][w + 1] : 0u);
        const unsigned hn = horiz3(shB[rr + 2][w],
                                   w > 0 ? shB[rr + 2][w - 1] : 0u,
                                   w < NWORDS - 1 ? shB[rr + 2][w + 1] : 0u);
        const unsigned e = shB[rr + 1][w] & ~(hp & hc & hn);
        shE[rr][w] = e;
        if (rr >= 1 && rr <= RPB)
            g_edgebits[m][(r0 + rr - 1) * NWORDS + w] = e;
    }
    __syncthreads();

    // per-pixel nearest edge per row + sliding vertical depth-1 min
    float prev2 = 0.0f, prev1 = 0.0f;
    #pragma unroll
    for (int rr = 0; rr < EROWS; rr++) {
        const unsigned ew = shE[rr][t];
        float g;
        if ((ew >> k) & 1u) {
            g = 0.0f;
        } else {
            float dl;
            const unsigned lw = (k > 0) ? (ew & ((1u << k) - 1u)) : 0u;
            if (lw) {
                dl = (float)(k - (31 - __clz(lw)));
            } else {
                int tt = t - 1;
                while (tt >= 0 && shE[rr][tt] == 0u) tt--;
                if (tt >= 0) dl = (float)(j - (tt * 32 + (31 - __clz(shE[rr][tt]))));
                else         dl = (float)j + 1e6f;
            }
            float dr;
            const unsigned rw = (k < 31) ? (ew & (0xFFFFFFFEu << k)) : 0u;
            if (rw) {
                dr = (float)(__ffs(rw) - 1 - k);
            } else {
                int tt = t + 1;
                while (tt < NWORDS && shE[rr][tt] == 0u) tt++;
                if (tt < NWORDS) dr = (float)((tt * 32 + (__ffs(shE[rr][tt]) - 1)) - j);
                else             dr = 1e6f - (float)j;
            }
            g = fminf(fminf(dl, dr), 1e6f);
        }
        const int gr = r0 - 1 + rr;                  // global row of this g
        const float cur = (gr >= 0 && gr < HH) ? g * g : 3e37f;

        if (rr >= 2) {
            const float dmin = fminf(prev1, fminf(prev2, cur) + 1.0f);
            g_D[m][(r0 + rr - 2) * WW + j] =
                (dmin <= 4.0f) ? (unsigned char)(int)dmin : (unsigned char)255;
        }
        prev2 = prev1; prev1 = cur;
    }
}

// ---------------------------------------------------------------------------
// Kernel B: byte-stream histogram; unresolved pixels handled by a ballot/
// shfl worklist with WARP-COOPERATIVE exact resolution (no serial-latency
// tail). sum = n1 + n2*sqrt2 + n3*sqrt3 + 2*n4 (+ exact rares), assembled in
// double from exact integer counts -> bit-deterministic. Final reduction
// fused via one packed u64 atomic (totally ordered; last block finishes).
// ---------------------------------------------------------------------------
__global__ void __launch_bounds__(B_THREADS) countpass_kernel(float* __restrict__ out)
{
    const int m   = blockIdx.y;
    const int tid = threadIdx.x;
    const int lane = tid & 31;
    const unsigned* __restrict__ Dw = (const unsigned*)g_D[m];
    const unsigned* __restrict__ Mw = g_edgebits[1 - m];
    const unsigned* __restrict__ Eb = g_edgebits[m];

    unsigned c1 = 0, c2 = 0, c3 = 0, c4 = 0;
    float racc = 0.0f;

    #pragma unroll
    for (int it = 0; it < B_ITERS; it++) {
        const int widx = it * (B_BLOCKS * B_THREADS) + blockIdx.x * B_THREADS + tid;
        const unsigned w     = Dw[widx];
        const unsigned mword = Mw[widx >> 3];
        const unsigned nib   = (mword >> ((widx & 7) * 4)) & 0xFu;
        const unsigned spread = (nib & 1u) | ((nib & 2u) << 7)
                              | ((nib & 4u) << 14) | ((nib & 8u) << 21);
        const unsigned mb = spread * 0xFFu;            // 0xFF per masked byte

        c1 += __popc(__vcmpeq4(w, 0x01010101u) & mb);  // raw counts are 8x
        c2 += __popc(__vcmpeq4(w, 0x02020202u) & mb);
        c3 += __popc(__vcmpeq4(w, 0x03030303u) & mb);
        c4 += __popc(__vcmpeq4(w, 0x04040404u) & mb);

        // rare: masked 255 bytes -> warp-cooperative exact resolution
        const unsigned un = __vcmpeq4(w, 0xFFFFFFFFu) & mb & 0x80808080u;
        unsigned pending = __ballot_sync(0xffffffffu, un != 0u);
        while (pending) {
            const int src = __ffs(pending) - 1;
            pending &= pending - 1u;
            unsigned uw       = __shfl_sync(0xffffffffu, un, src);
            const int wsrc    = __shfl_sync(0xffffffffu, widx, src);
            while (uw) {
                const int bit = __ffs(uw) - 1;
                uw &= uw - 1u;
                const int p = wsrc * 4 + (bit >> 3);
                const float b2 = warp_edt2(Eb, p >> 10, p & (WW - 1));
                if (lane == src) racc += sqrtf(b2);
                uw = __shfl_sync(0xffffffffu, uw, src);  // keep loop warp-uniform
            }
        }
    }

    // pack counts (block max < 2^16 per field) and reduce
    unsigned long long pc = (unsigned long long)(c1 >> 3)
                          | ((unsigned long long)(c2 >> 3) << 16)
                          | ((unsigned long long)(c3 >> 3) << 32)
                          | ((unsigned long long)(c4 >> 3) << 48);
    #pragma unroll
    for (int o = 16; o > 0; o >>= 1) {
        pc   += __shfl_down_sync(0xffffffffu, pc, o);
        racc += __shfl_down_sync(0xffffffffu, racc, o);
    }

    __shared__ unsigned long long wp[32];
    __shared__ float              wr[32];
    if (lane == 0) { wp[tid >> 5] = pc; wr[tid >> 5] = racc; }
    __syncthreads();

    if (tid == 0) {
        unsigned long long tot = 0; float fr = 0.0f;
        #pragma unroll
        for (int i = 0; i < 32; i++) { tot += wp[i]; fr += wr[i]; }
        const double n1 = (double)(tot & 0xFFFFULL);
        const double n2 = (double)((tot >> 16) & 0xFFFFULL);
        const double n3 = (double)((tot >> 32) & 0xFFFFULL);
        const double n4 = (double)((tot >> 48) & 0xFFFFULL);
        const double bs = n1
                        + n2 * 1.4142135623730951
                        + n3 * 1.7320508075688772
                        + n4 * 2.0
                        + (double)fr;

        const unsigned long long vfix   = (unsigned long long)(bs * FIXSCALE + 0.5);
        const unsigned long long packed = (1ULL << 48) | vfix;
        const unsigned long long old    = atomicAdd(&g_acc, packed);

        if ((old >> 48) == (unsigned long long)(NBLK_TOTAL - 1)) {
            const unsigned long long total = (old & 0xFFFFFFFFFFFFULL) + vfix;
            const float loss =
                (float)((double)total * (1.0 / FIXSCALE)) / (2.0f * (float)NPIX);
            out[0] = 1.0f / (1.0f + expf(-loss));
        }
    }
}

// ---------------------------------------------------------------------------
extern "C" void kernel_launch(void* const* d_in, const int* in_sizes, int n_in,
                              void* d_out, int out_size)
{
    const float* preds   = (const float*)d_in[0];
    const float* targets = (const float*)d_in[1];
    float* out = (float*)d_out;
    (void)in_sizes; (void)n_in; (void)out_size;

    dim3 gridA(HH / RPB, 2);
    edges_rowdist_kernel<<<gridA, WW>>>(preds, targets);

    dim3 gridB(B_BLOCKS, 2);
    countpass_kernel<<<gridB, B_THREADS>>>(out);
}

// round 16
// speedup vs baseline: 1.0934x; 1.0934x over previous
#include <cuda_runtime.h>
#include <math.h>

#define HH 1024
#define WW 1024
#define NPIX (HH * WW)
#define NWORDS 32                 // packed words per row
#define RPB 8                     // output rows per block in kernel A
#define LROWS (RPB + 6)           // seg rows loaded: r0-3 .. r0+10
#define EROWS (RPB + 4)           // edge rows computed: r0-2 .. r0+9

#define B_THREADS 256
#define B_BLOCKS 256              // x-blocks per image
#define B_ITERS (NPIX / 4 / (B_BLOCKS * B_THREADS))   // 4
#define NBLK_TOTAL (B_BLOCKS * 2)                     // 512
#define FIXSCALE 1048576.0        // 2^20 fixed point

// Scratch (no allocations allowed anywhere)
__device__ unsigned int       g_edgebits[2][HH * NWORDS];  // 256 KB
__device__ unsigned char      g_D[2][NPIX];                // 2 MB: D2 code in {0,1,2,4,5,8,9}, 255=unresolved
__device__ unsigned long long g_acc;   // [63:48] block count, [47:0] fixed-point sum

__device__ __forceinline__ unsigned horiz3(unsigned wv, unsigned wl, unsigned wr) {
    return wv & ((wv << 1) | (wl >> 31)) & ((wv >> 1) | (wr << 31));
}

// exact per-row nearest-edge distance from the packed edge bitmap (global),
// replicating the reference's 1e6 fp32 defaults bit-for-bit. Cold path only.
__device__ float row_g(const unsigned* __restrict__ row, int c)
{
    const int t = c >> 5, k = c & 31;
    const unsigned wc = row[t];
    const unsigned wl = (t > 0) ? row[t - 1] : 0u;
    const unsigned wr2 = (t < NWORDS - 1) ? row[t + 1] : 0u;
    const unsigned long long L = ((unsigned long long)wc << 32) | wl;   // pixel at bit 32+k
    const unsigned long long R = ((unsigned long long)wr2 << 32) | wc;  // pixel at bit k
    const unsigned long long lm = L & (~0ULL >> (31 - k));
    const unsigned long long rm = R & (~0ULL << k);
    float dl, dr;
    if (lm) {
        dl = (float)(__clzll((long long)lm) - (31 - k));
    } else {
        int tt = t - 2;
        while (tt >= 0 && row[tt] == 0u) tt--;
        if (tt >= 0) dl = (float)(c - (tt * 32 + (31 - __clz(row[tt]))));
        else         dl = (float)c + 1e6f;          // reference default, exact fp32
    }
    if (rm) {
        dr = (float)(__ffsll((long long)rm) - 1 - k);
    } else {
        int tt = t + 2;
        while (tt < NWORDS && row[tt] == 0u) tt++;
        if (tt < NWORDS) dr = (float)((tt * 32 + (__ffs(row[tt]) - 1)) - c);
        else             dr = 1e6f - (float)c;      // reference default, exact fp32
    }
    return fminf(fminf(dl, dr), 1e6f);
}

// exact column lower-envelope for one pixel, recomputed from edge bits.
// Same candidates/prune as the reference. Executed ~never (P ~ 2^-27/pixel).
__device__ float edt2_exact(const unsigned* __restrict__ eb, int r, int c)
{
    float g = row_g(eb + r * NWORDS, c);
    float best = g * g;
    for (int d = 1;; d++) {
        const float dd = (float)(d * d);
        if (dd >= best) break;
        bool any = false;
        if (r - d >= 0) { const float gu = row_g(eb + (r - d) * NWORDS, c); best = fminf(best, gu * gu + dd); any = true; }
        if (r + d < HH) { const float gd = row_g(eb + (r + d) * NWORDS, c); best = fminf(best, gd * gd + dd); any = true; }
        if (!any) break;
    }
    return best;
}

// ---------------------------------------------------------------------------
// Kernel A: bit-packed edges + per-row 1D distance + vertical DEPTH-2 min:
//   D2 = min(g2[r], min(g2[r-1],g2[r+1])+1, min(g2[r-2],g2[r+2])+4)
// D2 <= 9 proves global optimality (all d>=3 candidates >= 9); resolved D2 is
// an exact small integer in {0,1,2,4,5,8,9}. Unresolved (P ~ 2^-27) -> 255.
// Sliding 5-value register window over the per-thread row loop.
// ---------------------------------------------------------------------------
__global__ void __launch_bounds__(WW, 2) edges_rowdist_kernel(
    const float* __restrict__ preds, const float* __restrict__ targets)
{
    const int r0 = blockIdx.x * RPB;
    const int m  = blockIdx.y;
    const int j  = threadIdx.x;
    const float* __restrict__ seg = (m == 0) ? preds : targets;

    // reset the packed accumulator for this replay (stream-ordered before B)
    if (blockIdx.x == 0 && m == 0 && j == 0) g_acc = 0ULL;

    __shared__ unsigned shB[LROWS][NWORDS];
    __shared__ unsigned shE[EROWS][NWORDS];

    const int t = j >> 5, k = j & 31;

    // load LROWS rows (batched for MLP), ballot-pack to bits
    float v[LROWS];
    #pragma unroll
    for (int rr = 0; rr < LROWS; rr++) {
        const int row = r0 + rr - 3;
        v[rr] = (row >= 0 && row < HH) ? seg[row * WW + j] : 0.0f;
    }
    #pragma unroll
    for (int rr = 0; rr < LROWS; rr++) {
        const unsigned b = __ballot_sync(0xffffffffu, v[rr] == 1.0f);
        if (k == 0) shB[rr][t] = b;
    }
    __syncthreads();

    // EROWS*NWORDS = 384 threads compute one edge word each
    if (j < EROWS * NWORDS) {
        const int w  = j & (NWORDS - 1);
        const int rr = j >> 5;            // 0..11 -> edge row r0-2+rr
        const unsigned hp = horiz3(shB[rr][w],
                                   w > 0 ? shB[rr][w - 1] : 0u,
                                   w < NWORDS - 1 ? shB[rr][w + 1] : 0u);
        const unsigned hc = horiz3(shB[rr + 1][w],
                                   w > 0 ? shB[rr + 1][w - 1] : 0u,
                                   w < NWORDS - 1 ? shB[rr + 1][w + 1] : 0u);
        const unsigned hn = horiz3(shB[rr + 2][w],
                                   w > 0 ? shB[rr + 2][w - 1] : 0u,
                                   w < NWORDS - 1 ? shB[rr + 2][w + 1] : 0u);
        const unsigned e = shB[rr + 1][w] & ~(hp & hc & hn);
        shE[rr][w] = e;
        // persist edge words for center rows r0..r0+RPB-1 (gr = r0-2+rr)
        if (rr >= 2 && rr <= RPB + 1)
            g_edgebits[m][(r0 + rr - 2) * NWORDS + w] = e;
    }
    __syncthreads();

    // per-pixel nearest edge per row + sliding vertical depth-2 min
    float p4 = 3e37f, p3 = 3e37f, p2 = 3e37f, p1 = 3e37f;
    #pragma unroll
    for (int rr = 0; rr < EROWS; rr++) {
        const unsigned ew = shE[rr][t];
        float g;
        if ((ew >> k) & 1u) {
            g = 0.0f;
        } else {
            float dl;
            const unsigned lw = (k > 0) ? (ew & ((1u << k) - 1u)) : 0u;
            if (lw) {
                dl = (float)(k - (31 - __clz(lw)));
            } else {
                int tt = t - 1;
                while (tt >= 0 && shE[rr][tt] == 0u) tt--;
                if (tt >= 0) dl = (float)(j - (tt * 32 + (31 - __clz(shE[rr][tt]))));
                else         dl = (float)j + 1e6f;
            }
            float dr;
            const unsigned rw = (k < 31) ? (ew & (0xFFFFFFFEu << k)) : 0u;
            if (rw) {
                dr = (float)(__ffs(rw) - 1 - k);
            } else {
                int tt = t + 1;
                while (tt < NWORDS && shE[rr][tt] == 0u) tt++;
                if (tt < NWORDS) dr = (float)((tt * 32 + (__ffs(shE[rr][tt]) - 1)) - j);
                else             dr = 1e6f - (float)j;
            }
            g = fminf(fminf(dl, dr), 1e6f);
        }
        const int gr = r0 - 2 + rr;                  // global row of this edge row
        const float cur = (gr >= 0 && gr < HH) ? g * g : 3e37f;

        if (rr >= 4) {
            // center row = r0 + rr - 4 (value p2); ±1 = p1/p3; ±2 = cur/p4
            const float dmin = fminf(p2,
                               fminf(fminf(p3, p1) + 1.0f,
                                     fminf(p4, cur) + 4.0f));
            g_D[m][(r0 + rr - 4) * WW + j] =
                (dmin <= 9.0f) ? (unsigned char)(int)dmin : (unsigned char)255;
        }
        p4 = p3; p3 = p2; p2 = p1; p1 = cur;
    }
}

// ---------------------------------------------------------------------------
// Kernel B: byte-stream histogram over codes {1,2,4,5,8,9} (code 0 adds 0).
// Per u32 word (4 pixels): expand 4 mask bits to byte lanes, 6x vcmpeq4+popc.
// sum = n1 + sqrt2*n2 + 2*n4 + sqrt5*n5 + sqrt8*n8 + 3*n9 (+ exact rares),
// assembled in double from exact integer counts -> bit-deterministic.
// Final reduction fused via one packed u64 atomic (totally ordered; the
// block seeing old_count == N-1 owns the exact total; no fences).
// ---------------------------------------------------------------------------
__global__ void __launch_bounds__(B_THREADS) countpass_kernel(float* __restrict__ out)
{
    const int m   = blockIdx.y;
    const int tid = threadIdx.x;
    const unsigned* __restrict__ Dw = (const unsigned*)g_D[m];
    const unsigned* __restrict__ Mw = g_edgebits[1 - m];
    const unsigned* __restrict__ Eb = g_edgebits[m];

    unsigned c1 = 0, c2 = 0, c4 = 0, c5 = 0, c8 = 0, c9 = 0;
    float racc = 0.0f;

    #pragma unroll
    for (int it = 0; it < B_ITERS; it++) {
        const int widx = it * (B_BLOCKS * B_THREADS) + blockIdx.x * B_THREADS + tid;
        const unsigned w     = Dw[widx];
        const unsigned mword = Mw[widx >> 3];
        const unsigned nib   = (mword >> ((widx & 7) * 4)) & 0xFu;
        const unsigned spread = (nib & 1u) | ((nib & 2u) << 7)
                              | ((nib & 4u) << 14) | ((nib & 8u) << 21);
        const unsigned mb = spread * 0xFFu;            // 0xFF per masked byte

        c1 += __popc(__vcmpeq4(w, 0x01010101u) & mb);  // raw counts are 8x
        c2 += __popc(__vcmpeq4(w, 0x02020202u) & mb);
        c4 += __popc(__vcmpeq4(w, 0x04040404u) & mb);
        c5 += __popc(__vcmpeq4(w, 0x05050505u) & mb);
        c8 += __popc(__vcmpeq4(w, 0x08080808u) & mb);
        c9 += __popc(__vcmpeq4(w, 0x09090909u) & mb);

        // essentially-never path: masked 255 byte -> exact recompute
        unsigned un = __vcmpeq4(w, 0xFFFFFFFFu) & mb & 0x80808080u;
        while (un) {
            const int bit = __ffs(un) - 1;
            un &= un - 1u;
            const int p = widx * 4 + (bit >> 3);
            racc += sqrtf(edt2_exact(Eb, p >> 10, p & (WW - 1)));
        }
    }

    // pack raw counts into two u64s (per-block field max 32768 < 2^16)
    unsigned long long pa = (unsigned long long)c1
                          | ((unsigned long long)c2 << 16)
                          | ((unsigned long long)c4 << 32)
                          | ((unsigned long long)c5 << 48);
    unsigned long long pb = (unsigned long long)c8
                          | ((unsigned long long)c9 << 16);
    #pragma unroll
    for (int o = 16; o > 0; o >>= 1) {
        pa   += __shfl_down_sync(0xffffffffu, pa, o);
        pb   += __shfl_down_sync(0xffffffffu, pb, o);
        racc += __shfl_down_sync(0xffffffffu, racc, o);
    }

    __shared__ unsigned long long wpa[B_THREADS / 32], wpb[B_THREADS / 32];
    __shared__ float              wr[B_THREADS / 32];
    if ((tid & 31) == 0) { wpa[tid >> 5] = pa; wpb[tid >> 5] = pb; wr[tid >> 5] = racc; }
    __syncthreads();

    if (tid == 0) {
        unsigned long long ta = 0, tb = 0; float fr = 0.0f;
        #pragma unroll
        for (int i = 0; i < B_THREADS / 32; i++) { ta += wpa[i]; tb += wpb[i]; fr += wr[i]; }
        const double n1 = (double)((ta       ) & 0xFFFFULL) * 0.125;
        const double n2 = (double)((ta >> 16) & 0xFFFFULL) * 0.125;
        const double n4 = (double)((ta >> 32) & 0xFFFFULL) * 0.125;
        const double n5 = (double)((ta >> 48) & 0xFFFFULL) * 0.125;
        const double n8 = (double)((tb       ) & 0xFFFFULL) * 0.125;
        const double n9 = (double)((tb >> 16) & 0xFFFFULL) * 0.125;
        const double bs = n1
                        + n2 * 1.4142135623730951   // sqrt(2)
                        + n4 * 2.0
                        + n5 * 2.23606797749979     // sqrt(5)
                        + n8 * 2.8284271247461903   // sqrt(8)
                        + n9 * 3.0
                        + (double)fr;

        const unsigned long long vfix   = (unsigned long long)(bs * FIXSCALE + 0.5);
        const unsigned long long packed = (1ULL << 48) | vfix;
        const unsigned long long old    = atomicAdd(&g_acc, packed);

        if ((old >> 48) == (unsigned long long)(NBLK_TOTAL - 1)) {
            const unsigned long long total = (old & 0xFFFFFFFFFFFFULL) + vfix;
            const float loss =
                (float)((double)total * (1.0 / FIXSCALE)) / (2.0f * (float)NPIX);
            out[0] = 1.0f / (1.0f + expf(-loss));
        }
    }
}

// ---------------------------------------------------------------------------
extern "C" void kernel_launch(void* const* d_in, const int* in_sizes, int n_in,
                              void* d_out, int out_size)
{
    const float* preds   = (const float*)d_in[0];
    const float* targets = (const float*)d_in[1];
    float* out = (float*)d_out;
    (void)in_sizes; (void)n_in; (void)out_size;

    dim3 gridA(HH / RPB, 2);
    edges_rowdist_kernel<<<gridA, WW>>>(preds, targets);

    dim3 gridB(B_BLOCKS, 2);
    countpass_kernel<<<gridB, B_THREADS>>>(out);
}

// round 17
// speedup vs baseline: 2.1607x; 1.9762x over previous
#include <cuda_runtime.h>
#include <math.h>

#define HH 1024
#define WW 1024
#define NWORDS 32                 // packed words per row
#define RPB 8                     // rows per block in kernel A
#define FULLMASK 0xffffffffu
#define FIXSCALE 1048576.0        // 2^20 fixed point
#define NBLK_TOTAL 256            // kernel B blocks

// Scratch (no allocations allowed anywhere)
__device__ unsigned int       g_edgebits[2][HH * NWORDS];  // 256 KB
__device__ unsigned long long g_acc;   // [63:48] block count, [47:0] fixed-point sum

__device__ __forceinline__ unsigned horiz3(unsigned wv, unsigned wl, unsigned wr) {
    return wv & ((wv << 1) | (wl >> 31)) & ((wv >> 1) | (wr << 31));
}

// horizontal dilation by s with word-boundary carries
__device__ __forceinline__ unsigned dil(unsigned e, unsigned l, unsigned r, int s) {
    return (e << s) | (l >> (32 - s)) | (e >> s) | (r << (32 - s));
}

// exact per-row nearest-edge distance from the packed edge bitmap (global),
// replicating the reference's 1e6 fp32 defaults bit-for-bit. Cold path only.
__device__ float row_g(const unsigned* __restrict__ row, int c)
{
    const int t = c >> 5, k = c & 31;
    const unsigned wc = row[t];
    const unsigned wl = (t > 0) ? row[t - 1] : 0u;
    const unsigned wr2 = (t < NWORDS - 1) ? row[t + 1] : 0u;
    const unsigned long long L = ((unsigned long long)wc << 32) | wl;   // pixel at bit 32+k
    const unsigned long long R = ((unsigned long long)wr2 << 32) | wc;  // pixel at bit k
    const unsigned long long lm = L & (~0ULL >> (31 - k));
    const unsigned long long rm = R & (~0ULL << k);
    float dl, dr;
    if (lm) {
        dl = (float)(__clzll((long long)lm) - (31 - k));
    } else {
        int tt = t - 2;
        while (tt >= 0 && row[tt] == 0u) tt--;
        if (tt >= 0) dl = (float)(c - (tt * 32 + (31 - __clz(row[tt]))));
        else         dl = (float)c + 1e6f;          // reference default, exact fp32
    }
    if (rm) {
        dr = (float)(__ffsll((long long)rm) - 1 - k);
    } else {
        int tt = t + 2;
        while (tt < NWORDS && row[tt] == 0u) tt++;
        if (tt < NWORDS) dr = (float)((tt * 32 + (__ffs(row[tt]) - 1)) - c);
        else             dr = 1e6f - (float)c;      // reference default, exact fp32
    }
    return fminf(fminf(dl, dr), 1e6f);
}

// exact column lower-envelope for one pixel, recomputed from edge bits.
// Same candidate set / prune as the reference. Cold path (P ~ 2^-29 /pixel).
__device__ float edt2_exact(const unsigned* __restrict__ eb, int r, int c)
{
    float g = row_g(eb + r * NWORDS, c);
    float best = g * g;
    for (int d = 1;; d++) {
        const float dd = (float)(d * d);
        if (dd >= best) break;
        bool any = false;
        if (r - d >= 0) { const float gu = row_g(eb + (r - d) * NWORDS, c); best = fminf(best, gu * gu + dd); any = true; }
        if (r + d < HH) { const float gd = row_g(eb + (r + d) * NWORDS, c); best = fminf(best, gd * gd + dd); any = true; }
        if (!any) break;
    }
    return best;
}

// ---------------------------------------------------------------------------
// Kernel A: bit-packed edge maps ONLY (no distance work at all).
// edges = seg & ~erode3x3(seg), computed word-wise from ballots.
// ---------------------------------------------------------------------------
__global__ void __launch_bounds__(WW) edges_kernel(
    const float* __restrict__ preds, const float* __restrict__ targets)
{
    const int r0 = blockIdx.x * RPB;
    const int m  = blockIdx.y;
    const int j  = threadIdx.x;
    const float* __restrict__ seg = (m == 0) ? preds : targets;

    // reset the packed accumulator for this replay (stream-ordered before B)
    if (blockIdx.x == 0 && m == 0 && j == 0) g_acc = 0ULL;

    __shared__ unsigned shB[RPB + 2][NWORDS];

    const int t = j >> 5, k = j & 31;

    float v[RPB + 2];
    #pragma unroll
    for (int rr = 0; rr < RPB + 2; rr++) {
        const int row = r0 + rr - 1;
        v[rr] = (row >= 0 && row < HH) ? seg[row * WW + j] : 0.0f;
    }
    #pragma unroll
    for (int rr = 0; rr < RPB + 2; rr++) {
        const unsigned b = __ballot_sync(FULLMASK, v[rr] == 1.0f);
        if (k == 0) shB[rr][t] = b;
    }
    __syncthreads();

    if (j < RPB * NWORDS) {
        const int w  = j & (NWORDS - 1);
        const int rr = j >> 5;            // NWORDS == 32
        const unsigned hp = horiz3(shB[rr][w],
                                   w > 0 ? shB[rr][w - 1] : 0u,
                                   w < NWORDS - 1 ? shB[rr][w + 1] : 0u);
        const unsigned hc = horiz3(shB[rr + 1][w],
                                   w > 0 ? shB[rr + 1][w - 1] : 0u,
                                   w < NWORDS - 1 ? shB[rr + 1][w + 1] : 0u);
        const unsigned hn = horiz3(shB[rr + 2][w],
                                   w > 0 ? shB[rr + 2][w - 1] : 0u,
                                   w < NWORDS - 1 ? shB[rr + 2][w + 1] : 0u);
        g_edgebits[m][(r0 + rr) * NWORDS + w] =
            shB[rr + 1][w] & ~(hp & hc & hn);
    }
}

// ---------------------------------------------------------------------------
// Kernel B: WORD-PARALLEL distance classification. One warp = one image row;
// lane = word column (32 pixels). From 7 edge rows (r-3..r+3, OOB = 0) build
// disjoint class masks for D2 in {0,1,2,4,5,8,9} via shifted ORs (complete
// enumeration of di^2+dj^2 <= 9; word-boundary carries via shfl, image
// borders via zero words -> no candidates, exactly right). popc the masked
// classes; unresolved bits (no edge in the radius-3 ball, P~2^-29) fall back
// to the exact per-pixel EDT from the bitmaps. Block sum assembled in double
// from exact integer counts -> bit-deterministic; one packed u64 atomic
// finishes (totally ordered; the block seeing old_count == N-1 writes out).
// ---------------------------------------------------------------------------
__global__ void __launch_bounds__(256) classify_kernel(float* __restrict__ out)
{
    const int bid  = blockIdx.x;
    const int m    = bid >> 7;                      // image
    const int warp = threadIdx.x >> 5;
    const int lane = threadIdx.x & 31;
    const int r    = (bid & 127) * 8 + warp;        // row 0..1023
    const unsigned* __restrict__ Eb = g_edgebits[m];
    const unsigned* __restrict__ Mw = g_edgebits[1 - m];

    // 7 edge rows for this word column
    unsigned e[7];
    #pragma unroll
    for (int o = 0; o < 7; o++) {
        const int rr = r + o - 3;
        e[o] = (rr >= 0 && rr < HH) ? Eb[rr * NWORDS + lane] : 0u;
    }
    const unsigned mask = Mw[r * NWORDS + lane];

    // neighbor words (image-edge words are zero: lanes 0/31 clamp to 0)
    unsigned l[7], rt[7];
    #pragma unroll
    for (int o = 1; o <= 5; o++) {
        const unsigned lu = __shfl_up_sync(FULLMASK, e[o], 1);
        const unsigned rd = __shfl_down_sync(FULLMASK, e[o], 1);
        l[o]  = (lane == 0)  ? 0u : lu;
        rt[o] = (lane == 31) ? 0u : rd;
    }

    // hit masks per distance value
    const unsigned h0   = e[3];
    const unsigned d0s1 = dil(e[3], l[3], rt[3], 1);
    const unsigned d0s2 = dil(e[3], l[3], rt[3], 2);
    const unsigned d0s3 = dil(e[3], l[3], rt[3], 3);
    const unsigned v1   = e[2] | e[4];
    const unsigned v1s1 = dil(e[2], l[2], rt[2], 1) | dil(e[4], l[4], rt[4], 1);
    const unsigned v1s2 = dil(e[2], l[2], rt[2], 2) | dil(e[4], l[4], rt[4], 2);
    const unsigned v2   = e[1] | e[5];
    const unsigned v2s1 = dil(e[1], l[1], rt[1], 1) | dil(e[5], l[5], rt[5], 1);
    const unsigned v2s2 = dil(e[1], l[1], rt[1], 2) | dil(e[5], l[5], rt[5], 2);
    const unsigned v3   = e[0] | e[6];

    const unsigned h1 = d0s1 | v1;     // D2 = 1
    const unsigned h2 = v1s1;          // D2 = 2
    const unsigned h4 = d0s2 | v2;     // D2 = 4
    const unsigned h5 = v1s2 | v2s1;   // D2 = 5
    const unsigned h8 = v2s2;          // D2 = 8
    const unsigned h9 = d0s3 | v3;     // D2 = 9

    // disjoint classes by cumulative exclusion (priority = increasing D2)
    unsigned t  = h0;
    const unsigned c1 = h1 & ~t; t |= h1;
    const unsigned c2 = h2 & ~t; t |= h2;
    const unsigned c4 = h4 & ~t; t |= h4;
    const unsigned c5 = h5 & ~t; t |= h5;
    const unsigned c8 = h8 & ~t; t |= h8;
    const unsigned c9 = h9 & ~t; t |= h9;
    unsigned un = mask & ~t;           // unresolved masked pixels (~never)

    unsigned n1 = __popc(c1 & mask);
    unsigned n2 = __popc(c2 & mask);
    unsigned n4 = __popc(c4 & mask);
    unsigned n5 = __popc(c5 & mask);
    unsigned n8 = __popc(c8 & mask);
    unsigned n9 = __popc(c9 & mask);

    float racc = 0.0f;
    while (un) {
        const int bit = __ffs(un) - 1;
        un &= un - 1u;
        racc += sqrtf(edt2_exact(Eb, r, lane * 32 + bit));
    }

    // pack counts (each <= 32/thread, <= 1024/warp, <= 8192/block < 2^16)
    unsigned long long pa = (unsigned long long)n1
                          | ((unsigned long long)n2 << 16)
                          | ((unsigned long long)n4 << 32)
                          | ((unsigned long long)n5 << 48);
    unsigned long long pb = (unsigned long long)n8
                          | ((unsigned long long)n9 << 16);
    #pragma unroll
    for (int o = 16; o > 0; o >>= 1) {
        pa   += __shfl_down_sync(FULLMASK, pa, o);
        pb   += __shfl_down_sync(FULLMASK, pb, o);
        racc += __shfl_down_sync(FULLMASK, racc, o);
    }

    __shared__ unsigned long long wpa[8], wpb[8];
    __shared__ float              wr[8];
    if (lane == 0) { wpa[warp] = pa; wpb[warp] = pb; wr[warp] = racc; }
    __syncthreads();

    if (threadIdx.x == 0) {
        unsigned long long ta = 0, tb = 0; float fr = 0.0f;
        #pragma unroll
        for (int i = 0; i < 8; i++) { ta += wpa[i]; tb += wpb[i]; fr += wr[i]; }
        const double bs =
              (double)((ta      ) & 0xFFFFULL)                        // n1 * 1
            + (double)((ta >> 16) & 0xFFFFULL) * 1.4142135623730951   // sqrt(2)
            + (double)((ta >> 32) & 0xFFFFULL) * 2.0
            + (double)((ta >> 48) & 0xFFFFULL) * 2.23606797749979     // sqrt(5)
            + (double)((tb      ) & 0xFFFFULL) * 2.8284271247461903   // sqrt(8)
            + (double)((tb >> 16) & 0xFFFFULL) * 3.0
            + (double)fr;

        const unsigned long long vfix   = (unsigned long long)(bs * FIXSCALE + 0.5);
        const unsigned long long packed = (1ULL << 48) | vfix;
        const unsigned long long old    = atomicAdd(&g_acc, packed);

        if ((old >> 48) == (unsigned long long)(NBLK_TOTAL - 1)) {
            const unsigned long long total = (old & 0xFFFFFFFFFFFFULL) + vfix;
            const float loss =
                (float)((double)total * (1.0 / FIXSCALE))
                / (2.0f * (float)(HH * WW));
            out[0] = 1.0f / (1.0f + expf(-loss));
        }
    }
}

// ---------------------------------------------------------------------------
extern "C" void kernel_launch(void* const* d_in, const int* in_sizes, int n_in,
                              void* d_out, int out_size)
{
    const float* preds   = (const float*)d_in[0];
    const float* targets = (const float*)d_in[1];
    float* out = (float*)d_out;
    (void)in_sizes; (void)n_in; (void)out_size;

    dim3 gridA(HH / RPB, 2);
    edges_kernel<<<gridA, WW>>>(preds, targets);

    classify_kernel<<<NBLK_TOTAL, 256>>>(out);
}